// round 1
// baseline (speedup 1.0000x reference)
#include <cuda_runtime.h>

#define LL   512
#define DD   64
#define MM   16
#define BB   64
#define OD   1024
#define XX   4
#define QKSCALE 0.125f

// Scratch for projected Q/K/V in [head][p][d] layout (head = x*16+m, p = folded pos)
__device__ float g_Q[BB * LL * DD];
__device__ float g_K[BB * LL * DD];
__device__ float g_V[BB * LL * DD];

// ---------------------------------------------------------------------------
// Projection: Y[r][n] = sum_k X[r][k] * W[n][k] + b[n]
// rows = 32768 (= B*L), K = 1024, N = 64.
// Output is written with the reshape/transpose permutation baked in:
//   row r -> b = r/512, l = r%512; x=b/16, m=l%16, p=(b%16)*32 + l/16,
//   head hh = x*16+m; dest = g[(hh*512 + p)*64 + n].
// ---------------------------------------------------------------------------
__global__ __launch_bounds__(256) void proj_kernel(
    const float* __restrict__ Xm, const float* __restrict__ W,
    const float* __restrict__ bias, float* __restrict__ Y)
{
    __shared__ float Xs[32][129];  // [kk][row], pad 1 -> conflict-free
    __shared__ float Ws[32][65];   // [kk][n]

    const int t    = threadIdx.x;
    const int row0 = blockIdx.x * 128;
    const int ty   = t >> 4;   // 0..15  (rows ty*8 .. ty*8+7)
    const int tx   = t & 15;   // 0..15  (cols tx*4 .. tx*4+3)

    float acc[8][4];
#pragma unroll
    for (int i = 0; i < 8; i++)
#pragma unroll
        for (int j = 0; j < 4; j++) acc[i][j] = 0.f;

    for (int k0 = 0; k0 < OD; k0 += 32) {
        // load X tile 128x32 (transposed into smem)
#pragma unroll
        for (int s = 0; s < 4; s++) {
            int v  = t + 256 * s;            // 0..1023 float4 units
            int r  = v >> 3;                 // 0..127
            int kk = (v & 7) << 2;           // 0,4,...,28
            float4 xv = *(const float4*)(Xm + (size_t)(row0 + r) * OD + k0 + kk);
            Xs[kk + 0][r] = xv.x; Xs[kk + 1][r] = xv.y;
            Xs[kk + 2][r] = xv.z; Xs[kk + 3][r] = xv.w;
        }
        // load W tile 64x32 (transposed into smem)
#pragma unroll
        for (int s = 0; s < 2; s++) {
            int v  = t + 256 * s;            // 0..511
            int n  = v >> 3;                 // 0..63
            int kk = (v & 7) << 2;
            float4 wv = *(const float4*)(W + (size_t)n * OD + k0 + kk);
            Ws[kk + 0][n] = wv.x; Ws[kk + 1][n] = wv.y;
            Ws[kk + 2][n] = wv.z; Ws[kk + 3][n] = wv.w;
        }
        __syncthreads();

#pragma unroll
        for (int kk = 0; kk < 32; kk++) {
            float a[8], b[4];
#pragma unroll
            for (int i = 0; i < 8; i++) a[i] = Xs[kk][ty * 8 + i];
#pragma unroll
            for (int j = 0; j < 4; j++) b[j] = Ws[kk][tx * 4 + j];
#pragma unroll
            for (int i = 0; i < 8; i++)
#pragma unroll
                for (int j = 0; j < 4; j++)
                    acc[i][j] = fmaf(a[i], b[j], acc[i][j]);
        }
        __syncthreads();
    }

    float b4[4];
#pragma unroll
    for (int j = 0; j < 4; j++) b4[j] = bias[tx * 4 + j];

#pragma unroll
    for (int i = 0; i < 8; i++) {
        int row = row0 + ty * 8 + i;
        int b   = row >> 9;        // /512
        int l   = row & 511;
        int x   = b >> 4;
        int m   = l & 15;
        int p   = ((b & 15) << 5) | (l >> 4);
        int hh  = (x << 4) | m;
        float4 o;
        o.x = acc[i][0] + b4[0];
        o.y = acc[i][1] + b4[1];
        o.z = acc[i][2] + b4[2];
        o.w = acc[i][3] + b4[3];
        *(float4*)(Y + ((size_t)hh * LL + p) * DD + tx * 4) = o;
    }
}

// ---------------------------------------------------------------------------
// Flash-style attention. One block = (head hh, q-tile of 64 rows).
// 256 threads: i0 = (t/16)*4 -> thread's 4 q-rows; lane = t%16.
//   S cols owned: k-cols { lane + 16*jj }  (strided, keeps smem conflicts low)
//   O cols owned: d { lane*4 .. lane*4+3 }
// Causal + V_len tile skipping; Q_len block/row zeroing.
// ---------------------------------------------------------------------------
#define ATTN_SMEM ((64*64 + 64*68 + 64*64 + 64*68) * 4)

__global__ __launch_bounds__(256) void attn_kernel(
    const int* __restrict__ Q_len, const int* __restrict__ V_len,
    float* __restrict__ out)
{
    const int hh = blockIdx.y;        // 0..63
    const int q0 = blockIdx.x << 6;   // q-tile start
    const int x  = hh >> 4;
    const int m  = hh & 15;
    const int qlen = Q_len[x];
    const int vlen = V_len[x];
    const int t    = threadIdx.x;
    const int i0   = (t >> 4) << 2;   // 0,4,...,60
    const int lane = t & 15;
    const int d0   = lane << 2;

    float* outb = out + (size_t)x * LL * OD + (size_t)m * DD;

    if (q0 >= qlen) {
#pragma unroll
        for (int s = 0; s < 4; s++) {
            int v  = t + 256 * s;          // 0..1023 float4 units
            int r  = v >> 4;               // 0..63
            int dd = (v & 15) << 2;
            *(float4*)(outb + (size_t)(q0 + r) * OD + dd) =
                make_float4(0.f, 0.f, 0.f, 0.f);
        }
        return;
    }

    extern __shared__ float sm[];
    float* Qs = sm;                    // [64][64]
    float* Ks = sm + 64 * 64;          // [64][68] padded
    float* Vs = Ks + 64 * 68;          // [64][64]
    float* Ps = Vs + 64 * 64;          // [64][68] padded

    const float* Qg = g_Q + ((size_t)hh * LL + q0) * DD;
#pragma unroll
    for (int s = 0; s < 4; s++) {
        int v  = t + 256 * s;
        int r  = v >> 4;
        int dd = (v & 15) << 2;
        *(float4*)&Qs[r * 64 + dd] = *(const float4*)(Qg + r * DD + dd);
    }

    float Oa[4][4];
    float mrow[4], lrow[4];
#pragma unroll
    for (int ii = 0; ii < 4; ii++) {
        mrow[ii] = -1e30f;
        lrow[ii] = 0.f;
#pragma unroll
        for (int dd = 0; dd < 4; dd++) Oa[ii][dd] = 0.f;
    }

    int kmax = min(q0 + 63, vlen - 1);   // highest key index needed
    int nkt  = kmax >> 6;                // inclusive tile bound

    for (int kt = 0; kt <= nkt; kt++) {
        const int k0 = kt << 6;
        __syncthreads();   // previous PV done before overwriting K/V
        const float* Kg = g_K + ((size_t)hh * LL + k0) * DD;
        const float* Vg = g_V + ((size_t)hh * LL + k0) * DD;
#pragma unroll
        for (int s = 0; s < 4; s++) {
            int v  = t + 256 * s;
            int r  = v >> 4;
            int dd = (v & 15) << 2;
            *(float4*)&Ks[r * 68 + dd] = *(const float4*)(Kg + r * DD + dd);
            *(float4*)&Vs[r * 64 + dd] = *(const float4*)(Vg + r * DD + dd);
        }
        __syncthreads();

        // ---- S = Q K^T (thread's 4 rows x 4 strided cols) ----
        float S4[4][4];
#pragma unroll
        for (int ii = 0; ii < 4; ii++)
#pragma unroll
            for (int jj = 0; jj < 4; jj++) S4[ii][jj] = 0.f;

#pragma unroll
        for (int kk = 0; kk < 64; kk += 4) {
            float4 a[4], bz[4];
#pragma unroll
            for (int ii = 0; ii < 4; ii++)
                a[ii] = *(const float4*)&Qs[(i0 + ii) * 64 + kk];
#pragma unroll
            for (int jj = 0; jj < 4; jj++)
                bz[jj] = *(const float4*)&Ks[(lane + 16 * jj) * 68 + kk];
#pragma unroll
            for (int ii = 0; ii < 4; ii++)
#pragma unroll
                for (int jj = 0; jj < 4; jj++) {
                    S4[ii][jj] = fmaf(a[ii].x, bz[jj].x, S4[ii][jj]);
                    S4[ii][jj] = fmaf(a[ii].y, bz[jj].y, S4[ii][jj]);
                    S4[ii][jj] = fmaf(a[ii].z, bz[jj].z, S4[ii][jj]);
                    S4[ii][jj] = fmaf(a[ii].w, bz[jj].w, S4[ii][jj]);
                }
        }

        // ---- mask + scale ----
#pragma unroll
        for (int ii = 0; ii < 4; ii++) {
            int q = q0 + i0 + ii;
#pragma unroll
            for (int jj = 0; jj < 4; jj++) {
                int k = k0 + lane + 16 * jj;
                bool valid = (k <= q) && (k < vlen);
                S4[ii][jj] = valid ? S4[ii][jj] * QKSCALE : -1e30f;
            }
        }

        // ---- online softmax (reduce over 16-lane groups) ----
#pragma unroll
        for (int ii = 0; ii < 4; ii++) {
            float tm = fmaxf(fmaxf(S4[ii][0], S4[ii][1]),
                             fmaxf(S4[ii][2], S4[ii][3]));
#pragma unroll
            for (int w = 1; w < 16; w <<= 1)
                tm = fmaxf(tm, __shfl_xor_sync(0xffffffffu, tm, w));
            float mn    = fmaxf(mrow[ii], tm);
            float alpha = __expf(mrow[ii] - mn);
            float rs = 0.f;
#pragma unroll
            for (int jj = 0; jj < 4; jj++) {
                float p = __expf(S4[ii][jj] - mn);
                S4[ii][jj] = p;
                rs += p;
            }
#pragma unroll
            for (int w = 1; w < 16; w <<= 1)
                rs += __shfl_xor_sync(0xffffffffu, rs, w);
            mrow[ii] = mn;
            lrow[ii] = lrow[ii] * alpha + rs;
#pragma unroll
            for (int dd = 0; dd < 4; dd++) Oa[ii][dd] *= alpha;
        }

        // ---- store P ----
#pragma unroll
        for (int ii = 0; ii < 4; ii++)
#pragma unroll
            for (int jj = 0; jj < 4; jj++)
                Ps[(i0 + ii) * 68 + lane + 16 * jj] = S4[ii][jj];
        __syncthreads();

        // ---- O += P V ----
#pragma unroll
        for (int j = 0; j < 64; j += 4) {
            float4 p4[4], v4[4];
#pragma unroll
            for (int ii = 0; ii < 4; ii++)
                p4[ii] = *(const float4*)&Ps[(i0 + ii) * 68 + j];
#pragma unroll
            for (int jj = 0; jj < 4; jj++)
                v4[jj] = *(const float4*)&Vs[(j + jj) * 64 + d0];
#pragma unroll
            for (int ii = 0; ii < 4; ii++) {
                Oa[ii][0] = fmaf(p4[ii].x, v4[0].x, Oa[ii][0]);
                Oa[ii][1] = fmaf(p4[ii].x, v4[0].y, Oa[ii][1]);
                Oa[ii][2] = fmaf(p4[ii].x, v4[0].z, Oa[ii][2]);
                Oa[ii][3] = fmaf(p4[ii].x, v4[0].w, Oa[ii][3]);
                Oa[ii][0] = fmaf(p4[ii].y, v4[1].x, Oa[ii][0]);
                Oa[ii][1] = fmaf(p4[ii].y, v4[1].y, Oa[ii][1]);
                Oa[ii][2] = fmaf(p4[ii].y, v4[1].z, Oa[ii][2]);
                Oa[ii][3] = fmaf(p4[ii].y, v4[1].w, Oa[ii][3]);
                Oa[ii][0] = fmaf(p4[ii].z, v4[2].x, Oa[ii][0]);
                Oa[ii][1] = fmaf(p4[ii].z, v4[2].y, Oa[ii][1]);
                Oa[ii][2] = fmaf(p4[ii].z, v4[2].z, Oa[ii][2]);
                Oa[ii][3] = fmaf(p4[ii].z, v4[2].w, Oa[ii][3]);
                Oa[ii][0] = fmaf(p4[ii].w, v4[3].x, Oa[ii][0]);
                Oa[ii][1] = fmaf(p4[ii].w, v4[3].y, Oa[ii][1]);
                Oa[ii][2] = fmaf(p4[ii].w, v4[3].z, Oa[ii][2]);
                Oa[ii][3] = fmaf(p4[ii].w, v4[3].w, Oa[ii][3]);
            }
        }
    }

    // ---- finalize + Q_len row mask ----
#pragma unroll
    for (int ii = 0; ii < 4; ii++) {
        int q = q0 + i0 + ii;
        float inv = 1.f / lrow[ii];
        float4 o;
        if (q < qlen) {
            o.x = Oa[ii][0] * inv;
            o.y = Oa[ii][1] * inv;
            o.z = Oa[ii][2] * inv;
            o.w = Oa[ii][3] * inv;
        } else {
            o = make_float4(0.f, 0.f, 0.f, 0.f);
        }
        *(float4*)(outb + (size_t)q * OD + d0) = o;
    }
}

// ---------------------------------------------------------------------------
extern "C" void kernel_launch(void* const* d_in, const int* in_sizes, int n_in,
                              void* d_out, int out_size)
{
    (void)in_sizes; (void)n_in; (void)out_size;
    const float* Qseq = (const float*)d_in[0];
    const float* Kseq = (const float*)d_in[1];
    const float* Vseq = (const float*)d_in[2];
    const int*   Qlen = (const int*)d_in[3];
    const int*   Vlen = (const int*)d_in[4];
    const float* WQw  = (const float*)d_in[5];
    const float* WQb  = (const float*)d_in[6];
    const float* WKw  = (const float*)d_in[7];
    const float* WKb  = (const float*)d_in[8];
    const float* WVw  = (const float*)d_in[9];
    const float* WVb  = (const float*)d_in[10];
    float* out = (float*)d_out;

    float *pQ = nullptr, *pK = nullptr, *pV = nullptr;
    cudaGetSymbolAddress((void**)&pQ, g_Q);
    cudaGetSymbolAddress((void**)&pK, g_K);
    cudaGetSymbolAddress((void**)&pV, g_V);

    cudaFuncSetAttribute(attn_kernel,
                         cudaFuncAttributeMaxDynamicSharedMemorySize, ATTN_SMEM);

    proj_kernel<<<256, 256>>>(Qseq, WQw, WQb, pQ);
    proj_kernel<<<256, 256>>>(Kseq, WKw, WKb, pK);
    proj_kernel<<<256, 256>>>(Vseq, WVw, WVb, pV);

    dim3 grid(8, 64);
    attn_kernel<<<grid, 256, ATTN_SMEM>>>(Qlen, Vlen, out);
}

// round 3
// speedup vs baseline: 2.2223x; 2.2223x over previous
#include <cuda_runtime.h>
#include <cuda_bf16.h>
#include <cstdint>

#define LL   512
#define DD   64
#define OD   1024
#define QKSCALE 0.125f

// Scratch for projected Q/K/V in [head][p][d] layout (head = x*16+m, p = folded pos)
__device__ float g_Q[64 * LL * DD];
__device__ float g_K[64 * LL * DD];
__device__ float g_V[64 * LL * DD];

// ---------------------------------------------------------------------------
// Tensor-core projection via mma.sync (bf16, hi/lo split for fp32 accuracy).
// CTA: 128 rows x 64 cols. 8 warps in 4x2 grid, each warp 32x32.
// smem: Ahi/Alo [128][72] bf16, Bhi/Blo [64][72] bf16 (72 = pad, 144B rows).
// ---------------------------------------------------------------------------
#define KCH   64
#define NIT   (OD / KCH)     // 16
#define ROWP  144            // padded row bytes (72 bf16)
#define A_HI  0
#define A_LO  18432
#define B_HI  36864
#define B_LO  46080
#define PROJ_SMEM 55296

__device__ __forceinline__ uint32_t smem_u32(const void* p) {
    uint32_t a;
    asm("{ .reg .u64 t; cvta.to.shared.u64 t, %1; cvt.u32.u64 %0, t; }"
        : "=r"(a) : "l"(p));
    return a;
}

__device__ __forceinline__ void ldm4(uint32_t* r, uint32_t addr) {
    asm volatile("ldmatrix.sync.aligned.m8n8.x4.shared.b16 {%0,%1,%2,%3}, [%4];"
                 : "=r"(r[0]), "=r"(r[1]), "=r"(r[2]), "=r"(r[3]) : "r"(addr));
}

__device__ __forceinline__ void mma_bf16(float* c, const uint32_t* a,
                                         const uint32_t* b) {
    asm volatile(
        "mma.sync.aligned.m16n8k16.row.col.f32.bf16.bf16.f32 "
        "{%0,%1,%2,%3}, {%4,%5,%6,%7}, {%8,%9}, {%0,%1,%2,%3};"
        : "+f"(c[0]), "+f"(c[1]), "+f"(c[2]), "+f"(c[3])
        : "r"(a[0]), "r"(a[1]), "r"(a[2]), "r"(a[3]), "r"(b[0]), "r"(b[1]));
}

__device__ __forceinline__ void split_store(char* smb, uint32_t hi_off,
                                            uint32_t lo_off, float4 v) {
    __nv_bfloat16 hx = __float2bfloat16(v.x);
    __nv_bfloat16 hy = __float2bfloat16(v.y);
    __nv_bfloat16 hz = __float2bfloat16(v.z);
    __nv_bfloat16 hw = __float2bfloat16(v.w);
    uint2 hv, lv;
    hv.x = (uint32_t)__bfloat16_as_ushort(hx) |
           ((uint32_t)__bfloat16_as_ushort(hy) << 16);
    hv.y = (uint32_t)__bfloat16_as_ushort(hz) |
           ((uint32_t)__bfloat16_as_ushort(hw) << 16);
    lv.x = (uint32_t)__bfloat16_as_ushort(__float2bfloat16(v.x - __bfloat162float(hx))) |
           ((uint32_t)__bfloat16_as_ushort(__float2bfloat16(v.y - __bfloat162float(hy))) << 16);
    lv.y = (uint32_t)__bfloat16_as_ushort(__float2bfloat16(v.z - __bfloat162float(hz))) |
           ((uint32_t)__bfloat16_as_ushort(__float2bfloat16(v.w - __bfloat162float(hw))) << 16);
    *(uint2*)(smb + hi_off) = hv;
    *(uint2*)(smb + lo_off) = lv;
}

__global__ __launch_bounds__(256) void proj_tc(
    const float* __restrict__ Qs, const float* __restrict__ Ks,
    const float* __restrict__ Vs,
    const float* __restrict__ WQ, const float* __restrict__ WK,
    const float* __restrict__ WV,
    const float* __restrict__ bQ, const float* __restrict__ bK,
    const float* __restrict__ bV,
    float* __restrict__ YQ, float* __restrict__ YK, float* __restrict__ YV)
{
    extern __shared__ char sm[];
    const int t    = threadIdx.x;
    const int wid  = t >> 5;
    const int lane = t & 31;
    const int wr   = wid & 3;   // warp row: 32 rows each
    const int wc   = wid >> 2;  // warp col: 32 cols each

    const float *X, *W, *bias;
    float* Y;
    if (blockIdx.y == 0)      { X = Qs; W = WQ; bias = bQ; Y = YQ; }
    else if (blockIdx.y == 1) { X = Ks; W = WK; bias = bK; Y = YK; }
    else                      { X = Vs; W = WV; bias = bV; Y = YV; }

    const int row0 = blockIdx.x * 128;
    const uint32_t sb = smem_u32(sm);

    // ldmatrix lane address components (byte offsets within a tile)
    // A: row = wr*32 + mt*16 + (lane&15); col = ks*32 + ((lane>>4)&1)*16
    const uint32_t a_row_off = (uint32_t)(wr * 32 + (lane & 15)) * ROWP
                             + ((lane >> 4) & 1) * 16;
    // B: n = nb*16 + (lane&7) + ((lane&16)>>1); col = ks*32 + ((lane&8)<<1)
    const uint32_t b_row_off = (uint32_t)((lane & 7) + ((lane & 16) >> 1)) * ROWP
                             + ((lane & 8) << 1);

    const int rA = t >> 4;    // 0..15
    const int cA = t & 15;    // float4 index in 64-float chunk row

    float acc[2][4][4];
#pragma unroll
    for (int mt = 0; mt < 2; mt++)
#pragma unroll
        for (int nt = 0; nt < 4; nt++)
#pragma unroll
            for (int j = 0; j < 4; j++) acc[mt][nt][j] = 0.f;

    for (int it = 0; it < NIT; ++it) {
        const int k0 = it * KCH;
        __syncthreads();   // previous chunk's mma done reading smem

        // X tile: 128 rows x 64 floats -> Ahi/Alo
#pragma unroll
        for (int p = 0; p < 8; p++) {
            int r = rA + p * 16;
            float4 xv = *(const float4*)(X + (size_t)(row0 + r) * OD + k0 + cA * 4);
            uint32_t off = (uint32_t)r * ROWP + cA * 8;
            split_store(sm, A_HI + off, A_LO + off, xv);
        }
        // W tile: 64 rows (n) x 64 floats (k) -> Bhi/Blo, natural [n][k]
#pragma unroll
        for (int p = 0; p < 4; p++) {
            int n = rA + p * 16;
            float4 wv = *(const float4*)(W + (size_t)n * OD + k0 + cA * 4);
            uint32_t off = (uint32_t)n * ROWP + cA * 8;
            split_store(sm, B_HI + off, B_LO + off, wv);
        }
        __syncthreads();

#pragma unroll
        for (int ks = 0; ks < 4; ks++) {
            uint32_t ah[2][4], al[2][4];
#pragma unroll
            for (int mt = 0; mt < 2; mt++) {
                uint32_t ao = a_row_off + (uint32_t)mt * 16 * ROWP + ks * 32;
                ldm4(ah[mt], sb + A_HI + ao);
                ldm4(al[mt], sb + A_LO + ao);
            }
#pragma unroll
            for (int nb = 0; nb < 2; nb++) {
                uint32_t bo = b_row_off + (uint32_t)(wc * 32 + nb * 16) * ROWP
                            + ks * 32;
                uint32_t bh[4], bl[4];
                ldm4(bh, sb + B_HI + bo);
                ldm4(bl, sb + B_LO + bo);
#pragma unroll
                for (int mt = 0; mt < 2; mt++) {
#pragma unroll
                    for (int h = 0; h < 2; h++) {   // nt = nb*2 + h
                        float* c = acc[mt][nb * 2 + h];
                        mma_bf16(c, ah[mt], bh + h * 2);
                        mma_bf16(c, ah[mt], bl + h * 2);
                        mma_bf16(c, al[mt], bh + h * 2);
                    }
                }
            }
        }
    }

    // Epilogue: bias + permuted store (view/transpose trick baked in)
#pragma unroll
    for (int nt = 0; nt < 4; nt++) {
        int n0 = wc * 32 + nt * 8 + (lane & 3) * 2;
        float b0 = bias[n0], b1 = bias[n0 + 1];
#pragma unroll
        for (int mt = 0; mt < 2; mt++) {
#pragma unroll
            for (int ro = 0; ro < 2; ro++) {
                int grow = row0 + wr * 32 + mt * 16 + (lane >> 2) + ro * 8;
                int b = grow >> 9, l = grow & 511;
                int x = b >> 4, m = l & 15, pp = ((b & 15) << 5) | (l >> 4);
                int hh = (x << 4) | m;
                float2 o;
                o.x = acc[mt][nt][ro * 2 + 0] + b0;
                o.y = acc[mt][nt][ro * 2 + 1] + b1;
                *(float2*)(Y + ((size_t)hh * LL + pp) * DD + n0) = o;
            }
        }
    }
}

// ---------------------------------------------------------------------------
// Flash-style attention (unchanged from R0 passing kernel).
// ---------------------------------------------------------------------------
#define ATTN_SMEM ((64*64 + 64*68 + 64*64 + 64*68) * 4)

__global__ __launch_bounds__(256) void attn_kernel(
    const int* __restrict__ Q_len, const int* __restrict__ V_len,
    float* __restrict__ out)
{
    const int hh = blockIdx.y;
    const int q0 = blockIdx.x << 6;
    const int x  = hh >> 4;
    const int m  = hh & 15;
    const int qlen = Q_len[x];
    const int vlen = V_len[x];
    const int t    = threadIdx.x;
    const int i0   = (t >> 4) << 2;
    const int lane = t & 15;
    const int d0   = lane << 2;

    float* outb = out + (size_t)x * LL * OD + (size_t)m * DD;

    if (q0 >= qlen) {
#pragma unroll
        for (int s = 0; s < 4; s++) {
            int v  = t + 256 * s;
            int r  = v >> 4;
            int dd = (v & 15) << 2;
            *(float4*)(outb + (size_t)(q0 + r) * OD + dd) =
                make_float4(0.f, 0.f, 0.f, 0.f);
        }
        return;
    }

    extern __shared__ float smf[];
    float* Qsm = smf;
    float* Ksm = smf + 64 * 64;
    float* Vsm = Ksm + 64 * 68;
    float* Psm = Vsm + 64 * 64;

    const float* Qg = g_Q + ((size_t)hh * LL + q0) * DD;
#pragma unroll
    for (int s = 0; s < 4; s++) {
        int v  = t + 256 * s;
        int r  = v >> 4;
        int dd = (v & 15) << 2;
        *(float4*)&Qsm[r * 64 + dd] = *(const float4*)(Qg + r * DD + dd);
    }

    float Oa[4][4];
    float mrow[4], lrow[4];
#pragma unroll
    for (int ii = 0; ii < 4; ii++) {
        mrow[ii] = -1e30f;
        lrow[ii] = 0.f;
#pragma unroll
        for (int dd = 0; dd < 4; dd++) Oa[ii][dd] = 0.f;
    }

    int kmax = min(q0 + 63, vlen - 1);
    int nkt  = kmax >> 6;

    for (int kt = 0; kt <= nkt; kt++) {
        const int k0 = kt << 6;
        __syncthreads();
        const float* Kg = g_K + ((size_t)hh * LL + k0) * DD;
        const float* Vg = g_V + ((size_t)hh * LL + k0) * DD;
#pragma unroll
        for (int s = 0; s < 4; s++) {
            int v  = t + 256 * s;
            int r  = v >> 4;
            int dd = (v & 15) << 2;
            *(float4*)&Ksm[r * 68 + dd] = *(const float4*)(Kg + r * DD + dd);
            *(float4*)&Vsm[r * 64 + dd] = *(const float4*)(Vg + r * DD + dd);
        }
        __syncthreads();

        float S4[4][4];
#pragma unroll
        for (int ii = 0; ii < 4; ii++)
#pragma unroll
            for (int jj = 0; jj < 4; jj++) S4[ii][jj] = 0.f;

#pragma unroll
        for (int kk = 0; kk < 64; kk += 4) {
            float4 a[4], bz[4];
#pragma unroll
            for (int ii = 0; ii < 4; ii++)
                a[ii] = *(const float4*)&Qsm[(i0 + ii) * 64 + kk];
#pragma unroll
            for (int jj = 0; jj < 4; jj++)
                bz[jj] = *(const float4*)&Ksm[(lane + 16 * jj) * 68 + kk];
#pragma unroll
            for (int ii = 0; ii < 4; ii++)
#pragma unroll
                for (int jj = 0; jj < 4; jj++) {
                    S4[ii][jj] = fmaf(a[ii].x, bz[jj].x, S4[ii][jj]);
                    S4[ii][jj] = fmaf(a[ii].y, bz[jj].y, S4[ii][jj]);
                    S4[ii][jj] = fmaf(a[ii].z, bz[jj].z, S4[ii][jj]);
                    S4[ii][jj] = fmaf(a[ii].w, bz[jj].w, S4[ii][jj]);
                }
        }

#pragma unroll
        for (int ii = 0; ii < 4; ii++) {
            int q = q0 + i0 + ii;
#pragma unroll
            for (int jj = 0; jj < 4; jj++) {
                int k = k0 + lane + 16 * jj;
                bool valid = (k <= q) && (k < vlen);
                S4[ii][jj] = valid ? S4[ii][jj] * QKSCALE : -1e30f;
            }
        }

#pragma unroll
        for (int ii = 0; ii < 4; ii++) {
            float tm = fmaxf(fmaxf(S4[ii][0], S4[ii][1]),
                             fmaxf(S4[ii][2], S4[ii][3]));
#pragma unroll
            for (int w = 1; w < 16; w <<= 1)
                tm = fmaxf(tm, __shfl_xor_sync(0xffffffffu, tm, w));
            float mn    = fmaxf(mrow[ii], tm);
            float alpha = __expf(mrow[ii] - mn);
            float rs = 0.f;
#pragma unroll
            for (int jj = 0; jj < 4; jj++) {
                float p = __expf(S4[ii][jj] - mn);
                S4[ii][jj] = p;
                rs += p;
            }
#pragma unroll
            for (int w = 1; w < 16; w <<= 1)
                rs += __shfl_xor_sync(0xffffffffu, rs, w);
            mrow[ii] = mn;
            lrow[ii] = lrow[ii] * alpha + rs;
#pragma unroll
            for (int dd = 0; dd < 4; dd++) Oa[ii][dd] *= alpha;
        }

#pragma unroll
        for (int ii = 0; ii < 4; ii++)
#pragma unroll
            for (int jj = 0; jj < 4; jj++)
                Psm[(i0 + ii) * 68 + lane + 16 * jj] = S4[ii][jj];
        __syncthreads();

#pragma unroll
        for (int j = 0; j < 64; j += 4) {
            float4 p4[4], v4[4];
#pragma unroll
            for (int ii = 0; ii < 4; ii++)
                p4[ii] = *(const float4*)&Psm[(i0 + ii) * 68 + j];
#pragma unroll
            for (int jj = 0; jj < 4; jj++)
                v4[jj] = *(const float4*)&Vsm[(j + jj) * 64 + d0];
#pragma unroll
            for (int ii = 0; ii < 4; ii++) {
                Oa[ii][0] = fmaf(p4[ii].x, v4[0].x, Oa[ii][0]);
                Oa[ii][1] = fmaf(p4[ii].x, v4[0].y, Oa[ii][1]);
                Oa[ii][2] = fmaf(p4[ii].x, v4[0].z, Oa[ii][2]);
                Oa[ii][3] = fmaf(p4[ii].x, v4[0].w, Oa[ii][3]);
                Oa[ii][0] = fmaf(p4[ii].y, v4[1].x, Oa[ii][0]);
                Oa[ii][1] = fmaf(p4[ii].y, v4[1].y, Oa[ii][1]);
                Oa[ii][2] = fmaf(p4[ii].y, v4[1].z, Oa[ii][2]);
                Oa[ii][3] = fmaf(p4[ii].y, v4[1].w, Oa[ii][3]);
                Oa[ii][0] = fmaf(p4[ii].z, v4[2].x, Oa[ii][0]);
                Oa[ii][1] = fmaf(p4[ii].z, v4[2].y, Oa[ii][1]);
                Oa[ii][2] = fmaf(p4[ii].z, v4[2].z, Oa[ii][2]);
                Oa[ii][3] = fmaf(p4[ii].z, v4[2].w, Oa[ii][3]);
                Oa[ii][0] = fmaf(p4[ii].w, v4[3].x, Oa[ii][0]);
                Oa[ii][1] = fmaf(p4[ii].w, v4[3].y, Oa[ii][1]);
                Oa[ii][2] = fmaf(p4[ii].w, v4[3].z, Oa[ii][2]);
                Oa[ii][3] = fmaf(p4[ii].w, v4[3].w, Oa[ii][3]);
            }
        }
    }

#pragma unroll
    for (int ii = 0; ii < 4; ii++) {
        int q = q0 + i0 + ii;
        float inv = 1.f / lrow[ii];
        float4 o;
        if (q < qlen) {
            o.x = Oa[ii][0] * inv;
            o.y = Oa[ii][1] * inv;
            o.z = Oa[ii][2] * inv;
            o.w = Oa[ii][3] * inv;
        } else {
            o = make_float4(0.f, 0.f, 0.f, 0.f);
        }
        *(float4*)(outb + (size_t)q * OD + d0) = o;
    }
}

// ---------------------------------------------------------------------------
extern "C" void kernel_launch(void* const* d_in, const int* in_sizes, int n_in,
                              void* d_out, int out_size)
{
    (void)in_sizes; (void)n_in; (void)out_size;
    const float* Qseq = (const float*)d_in[0];
    const float* Kseq = (const float*)d_in[1];
    const float* Vseq = (const float*)d_in[2];
    const int*   Qlen = (const int*)d_in[3];
    const int*   Vlen = (const int*)d_in[4];
    const float* WQw  = (const float*)d_in[5];
    const float* WQb  = (const float*)d_in[6];
    const float* WKw  = (const float*)d_in[7];
    const float* WKb  = (const float*)d_in[8];
    const float* WVw  = (const float*)d_in[9];
    const float* WVb  = (const float*)d_in[10];
    float* out = (float*)d_out;

    float *pQ = nullptr, *pK = nullptr, *pV = nullptr;
    cudaGetSymbolAddress((void**)&pQ, g_Q);
    cudaGetSymbolAddress((void**)&pK, g_K);
    cudaGetSymbolAddress((void**)&pV, g_V);

    cudaFuncSetAttribute(proj_tc,
                         cudaFuncAttributeMaxDynamicSharedMemorySize, PROJ_SMEM);
    cudaFuncSetAttribute(attn_kernel,
                         cudaFuncAttributeMaxDynamicSharedMemorySize, ATTN_SMEM);

    dim3 pg(256, 3);
    proj_tc<<<pg, 256, PROJ_SMEM>>>(Qseq, Kseq, Vseq,
                                    WQw, WKw, WVw,
                                    WQb, WKb, WVb,
                                    pQ, pK, pV);

    dim3 grid(8, 64);
    attn_kernel<<<grid, 256, ATTN_SMEM>>>(Qlen, Vlen, out);
}

// round 4
// speedup vs baseline: 2.5677x; 1.1554x over previous
#include <cuda_runtime.h>
#include <cuda_bf16.h>
#include <cstdint>

#define LL   512
#define DD   64
#define OD   1024
#define QKSCALE 0.125f

// Scratch for projected Q/K/V in [head][p][d] layout (head = x*16+m, p = folded pos)
__device__ float g_Q[64 * LL * DD];
__device__ float g_K[64 * LL * DD];
__device__ float g_V[64 * LL * DD];

// ---------------------------------------------------------------------------
// Tensor-core projection via mma.sync (bf16, hi/lo split for fp32 accuracy).
// CTA: 128 rows x 64 cols. 8 warps in 4x2 grid, each warp 32x32.
// smem: Ahi/Alo [128][72] bf16, Bhi/Blo [64][72] bf16 (72 = pad, 144B rows).
// Software pipelined: LDG of chunk i+1 issued before MMA of chunk i.
// ---------------------------------------------------------------------------
#define KCH   64
#define NIT   (OD / KCH)     // 16
#define ROWP  144            // padded row bytes (72 bf16)
#define A_HI  0
#define A_LO  18432
#define B_HI  36864
#define B_LO  46080
#define PROJ_SMEM 55296

__device__ __forceinline__ uint32_t smem_u32(const void* p) {
    uint32_t a;
    asm("{ .reg .u64 t; cvta.to.shared.u64 t, %1; cvt.u32.u64 %0, t; }"
        : "=r"(a) : "l"(p));
    return a;
}

__device__ __forceinline__ void ldm4(uint32_t* r, uint32_t addr) {
    asm volatile("ldmatrix.sync.aligned.m8n8.x4.shared.b16 {%0,%1,%2,%3}, [%4];"
                 : "=r"(r[0]), "=r"(r[1]), "=r"(r[2]), "=r"(r[3]) : "r"(addr));
}

__device__ __forceinline__ void mma_bf16(float* c, const uint32_t* a,
                                         const uint32_t* b) {
    asm volatile(
        "mma.sync.aligned.m16n8k16.row.col.f32.bf16.bf16.f32 "
        "{%0,%1,%2,%3}, {%4,%5,%6,%7}, {%8,%9}, {%0,%1,%2,%3};"
        : "+f"(c[0]), "+f"(c[1]), "+f"(c[2]), "+f"(c[3])
        : "r"(a[0]), "r"(a[1]), "r"(a[2]), "r"(a[3]), "r"(b[0]), "r"(b[1]));
}

__device__ __forceinline__ void split_store(char* smb, uint32_t hi_off,
                                            uint32_t lo_off, float4 v) {
    __nv_bfloat16 hx = __float2bfloat16(v.x);
    __nv_bfloat16 hy = __float2bfloat16(v.y);
    __nv_bfloat16 hz = __float2bfloat16(v.z);
    __nv_bfloat16 hw = __float2bfloat16(v.w);
    uint2 hv, lv;
    hv.x = (uint32_t)__bfloat16_as_ushort(hx) |
           ((uint32_t)__bfloat16_as_ushort(hy) << 16);
    hv.y = (uint32_t)__bfloat16_as_ushort(hz) |
           ((uint32_t)__bfloat16_as_ushort(hw) << 16);
    lv.x = (uint32_t)__bfloat16_as_ushort(__float2bfloat16(v.x - __bfloat162float(hx))) |
           ((uint32_t)__bfloat16_as_ushort(__float2bfloat16(v.y - __bfloat162float(hy))) << 16);
    lv.y = (uint32_t)__bfloat16_as_ushort(__float2bfloat16(v.z - __bfloat162float(hz))) |
           ((uint32_t)__bfloat16_as_ushort(__float2bfloat16(v.w - __bfloat162float(hw))) << 16);
    *(uint2*)(smb + hi_off) = hv;
    *(uint2*)(smb + lo_off) = lv;
}

__global__ __launch_bounds__(256, 2) void proj_tc(
    const float* __restrict__ Qs, const float* __restrict__ Ks,
    const float* __restrict__ Vs,
    const float* __restrict__ WQ, const float* __restrict__ WK,
    const float* __restrict__ WV,
    const float* __restrict__ bQ, const float* __restrict__ bK,
    const float* __restrict__ bV,
    float* __restrict__ YQ, float* __restrict__ YK, float* __restrict__ YV)
{
    extern __shared__ char sm[];
    const int t    = threadIdx.x;
    const int wid  = t >> 5;
    const int lane = t & 31;
    const int wr   = wid & 3;   // warp row: 32 rows each
    const int wc   = wid >> 2;  // warp col: 32 cols each

    const float *X, *W, *bias;
    float* Y;
    if (blockIdx.y == 0)      { X = Qs; W = WQ; bias = bQ; Y = YQ; }
    else if (blockIdx.y == 1) { X = Ks; W = WK; bias = bK; Y = YK; }
    else                      { X = Vs; W = WV; bias = bV; Y = YV; }

    const int row0 = blockIdx.x * 128;
    const uint32_t sb = smem_u32(sm);

    // ldmatrix lane address components (byte offsets within a tile)
    const uint32_t a_row_off = (uint32_t)(wr * 32 + (lane & 15)) * ROWP
                             + ((lane >> 4) & 1) * 16;
    const uint32_t b_row_off = (uint32_t)((lane & 7) + ((lane & 16) >> 1)) * ROWP
                             + ((lane & 8) << 1);

    const int rA = t >> 4;    // 0..15
    const int cA = t & 15;    // float4 index in 64-float chunk row

    const float* xbase = X + (size_t)(row0 + rA) * OD + cA * 4;
    const float* wbase = W + (size_t)rA * OD + cA * 4;

    float acc[2][4][4];
#pragma unroll
    for (int mt = 0; mt < 2; mt++)
#pragma unroll
        for (int nt = 0; nt < 4; nt++)
#pragma unroll
            for (int j = 0; j < 4; j++) acc[mt][nt][j] = 0.f;

    // Prologue: load chunk 0 into registers
    float4 xr[8], wreg[4];
#pragma unroll
    for (int p = 0; p < 8; p++)
        xr[p] = *(const float4*)(xbase + (size_t)(p * 16) * OD);
#pragma unroll
    for (int p = 0; p < 4; p++)
        wreg[p] = *(const float4*)(wbase + (size_t)(p * 16) * OD);

    for (int it = 0; it < NIT; ++it) {
        // Store current chunk's registers to smem (bf16 hi/lo split)
#pragma unroll
        for (int p = 0; p < 8; p++) {
            uint32_t off = (uint32_t)(rA + p * 16) * ROWP + cA * 8;
            split_store(sm, A_HI + off, A_LO + off, xr[p]);
        }
#pragma unroll
        for (int p = 0; p < 4; p++) {
            uint32_t off = (uint32_t)(rA + p * 16) * ROWP + cA * 8;
            split_store(sm, B_HI + off, B_LO + off, wreg[p]);
        }
        __syncthreads();

        // Issue next chunk's LDGs now — they overlap the MMA block below.
        if (it + 1 < NIT) {
            const int k1 = (it + 1) * KCH;
#pragma unroll
            for (int p = 0; p < 8; p++)
                xr[p] = *(const float4*)(xbase + (size_t)(p * 16) * OD + k1);
#pragma unroll
            for (int p = 0; p < 4; p++)
                wreg[p] = *(const float4*)(wbase + (size_t)(p * 16) * OD + k1);
        }

#pragma unroll
        for (int ks = 0; ks < 4; ks++) {
            uint32_t ah[2][4], al[2][4];
#pragma unroll
            for (int mt = 0; mt < 2; mt++) {
                uint32_t ao = a_row_off + (uint32_t)mt * 16 * ROWP + ks * 32;
                ldm4(ah[mt], sb + A_HI + ao);
                ldm4(al[mt], sb + A_LO + ao);
            }
#pragma unroll
            for (int nb = 0; nb < 2; nb++) {
                uint32_t bo = b_row_off + (uint32_t)(wc * 32 + nb * 16) * ROWP
                            + ks * 32;
                uint32_t bh[4], bl[4];
                ldm4(bh, sb + B_HI + bo);
                ldm4(bl, sb + B_LO + bo);
#pragma unroll
                for (int mt = 0; mt < 2; mt++) {
#pragma unroll
                    for (int h = 0; h < 2; h++) {   // nt = nb*2 + h
                        float* c = acc[mt][nb * 2 + h];
                        mma_bf16(c, ah[mt], bh + h * 2);
                        mma_bf16(c, ah[mt], bl + h * 2);
                        mma_bf16(c, al[mt], bh + h * 2);
                    }
                }
            }
        }
        __syncthreads();   // all warps done reading smem before next STS
    }

    // Epilogue: bias + permuted store (view/transpose trick baked in)
#pragma unroll
    for (int nt = 0; nt < 4; nt++) {
        int n0 = wc * 32 + nt * 8 + (lane & 3) * 2;
        float b0 = bias[n0], b1 = bias[n0 + 1];
#pragma unroll
        for (int mt = 0; mt < 2; mt++) {
#pragma unroll
            for (int ro = 0; ro < 2; ro++) {
                int grow = row0 + wr * 32 + mt * 16 + (lane >> 2) + ro * 8;
                int b = grow >> 9, l = grow & 511;
                int x = b >> 4, m = l & 15, pp = ((b & 15) << 5) | (l >> 4);
                int hh = (x << 4) | m;
                float2 o;
                o.x = acc[mt][nt][ro * 2 + 0] + b0;
                o.y = acc[mt][nt][ro * 2 + 1] + b1;
                *(float2*)(Y + ((size_t)hh * LL + pp) * DD + n0) = o;
            }
        }
    }
}

// ---------------------------------------------------------------------------
// Flash-style attention (compute unchanged; LPT block order: heavy q-tiles
// launch first; grid.x = head so same-cost CTAs are contiguous).
// ---------------------------------------------------------------------------
#define ATTN_SMEM ((64*64 + 64*68 + 64*64 + 64*68) * 4)

__global__ __launch_bounds__(256) void attn_kernel(
    const int* __restrict__ Q_len, const int* __restrict__ V_len,
    float* __restrict__ out)
{
    const int hh = blockIdx.x;              // 0..63
    const int q0 = (7 - blockIdx.y) << 6;   // heavy tiles first
    const int x  = hh >> 4;
    const int m  = hh & 15;
    const int qlen = Q_len[x];
    const int vlen = V_len[x];
    const int t    = threadIdx.x;
    const int i0   = (t >> 4) << 2;
    const int lane = t & 15;
    const int d0   = lane << 2;

    float* outb = out + (size_t)x * LL * OD + (size_t)m * DD;

    if (q0 >= qlen) {
#pragma unroll
        for (int s = 0; s < 4; s++) {
            int v  = t + 256 * s;
            int r  = v >> 4;
            int dd = (v & 15) << 2;
            *(float4*)(outb + (size_t)(q0 + r) * OD + dd) =
                make_float4(0.f, 0.f, 0.f, 0.f);
        }
        return;
    }

    extern __shared__ float smf[];
    float* Qsm = smf;
    float* Ksm = smf + 64 * 64;
    float* Vsm = Ksm + 64 * 68;
    float* Psm = Vsm + 64 * 64;

    const float* Qg = g_Q + ((size_t)hh * LL + q0) * DD;
#pragma unroll
    for (int s = 0; s < 4; s++) {
        int v  = t + 256 * s;
        int r  = v >> 4;
        int dd = (v & 15) << 2;
        *(float4*)&Qsm[r * 64 + dd] = *(const float4*)(Qg + r * DD + dd);
    }

    float Oa[4][4];
    float mrow[4], lrow[4];
#pragma unroll
    for (int ii = 0; ii < 4; ii++) {
        mrow[ii] = -1e30f;
        lrow[ii] = 0.f;
#pragma unroll
        for (int dd = 0; dd < 4; dd++) Oa[ii][dd] = 0.f;
    }

    int kmax = min(q0 + 63, vlen - 1);
    int nkt  = kmax >> 6;

    for (int kt = 0; kt <= nkt; kt++) {
        const int k0 = kt << 6;
        __syncthreads();
        const float* Kg = g_K + ((size_t)hh * LL + k0) * DD;
        const float* Vg = g_V + ((size_t)hh * LL + k0) * DD;
#pragma unroll
        for (int s = 0; s < 4; s++) {
            int v  = t + 256 * s;
            int r  = v >> 4;
            int dd = (v & 15) << 2;
            *(float4*)&Ksm[r * 68 + dd] = *(const float4*)(Kg + r * DD + dd);
            *(float4*)&Vsm[r * 64 + dd] = *(const float4*)(Vg + r * DD + dd);
        }
        __syncthreads();

        float S4[4][4];
#pragma unroll
        for (int ii = 0; ii < 4; ii++)
#pragma unroll
            for (int jj = 0; jj < 4; jj++) S4[ii][jj] = 0.f;

#pragma unroll
        for (int kk = 0; kk < 64; kk += 4) {
            float4 a[4], bz[4];
#pragma unroll
            for (int ii = 0; ii < 4; ii++)
                a[ii] = *(const float4*)&Qsm[(i0 + ii) * 64 + kk];
#pragma unroll
            for (int jj = 0; jj < 4; jj++)
                bz[jj] = *(const float4*)&Ksm[(lane + 16 * jj) * 68 + kk];
#pragma unroll
            for (int ii = 0; ii < 4; ii++)
#pragma unroll
                for (int jj = 0; jj < 4; jj++) {
                    S4[ii][jj] = fmaf(a[ii].x, bz[jj].x, S4[ii][jj]);
                    S4[ii][jj] = fmaf(a[ii].y, bz[jj].y, S4[ii][jj]);
                    S4[ii][jj] = fmaf(a[ii].z, bz[jj].z, S4[ii][jj]);
                    S4[ii][jj] = fmaf(a[ii].w, bz[jj].w, S4[ii][jj]);
                }
        }

#pragma unroll
        for (int ii = 0; ii < 4; ii++) {
            int q = q0 + i0 + ii;
#pragma unroll
            for (int jj = 0; jj < 4; jj++) {
                int k = k0 + lane + 16 * jj;
                bool valid = (k <= q) && (k < vlen);
                S4[ii][jj] = valid ? S4[ii][jj] * QKSCALE : -1e30f;
            }
        }

#pragma unroll
        for (int ii = 0; ii < 4; ii++) {
            float tm = fmaxf(fmaxf(S4[ii][0], S4[ii][1]),
                             fmaxf(S4[ii][2], S4[ii][3]));
#pragma unroll
            for (int w = 1; w < 16; w <<= 1)
                tm = fmaxf(tm, __shfl_xor_sync(0xffffffffu, tm, w));
            float mn    = fmaxf(mrow[ii], tm);
            float alpha = __expf(mrow[ii] - mn);
            float rs = 0.f;
#pragma unroll
            for (int jj = 0; jj < 4; jj++) {
                float p = __expf(S4[ii][jj] - mn);
                S4[ii][jj] = p;
                rs += p;
            }
#pragma unroll
            for (int w = 1; w < 16; w <<= 1)
                rs += __shfl_xor_sync(0xffffffffu, rs, w);
            mrow[ii] = mn;
            lrow[ii] = lrow[ii] * alpha + rs;
#pragma unroll
            for (int dd = 0; dd < 4; dd++) Oa[ii][dd] *= alpha;
        }

#pragma unroll
        for (int ii = 0; ii < 4; ii++)
#pragma unroll
            for (int jj = 0; jj < 4; jj++)
                Psm[(i0 + ii) * 68 + lane + 16 * jj] = S4[ii][jj];
        __syncthreads();

#pragma unroll
        for (int j = 0; j < 64; j += 4) {
            float4 p4[4], v4[4];
#pragma unroll
            for (int ii = 0; ii < 4; ii++)
                p4[ii] = *(const float4*)&Psm[(i0 + ii) * 68 + j];
#pragma unroll
            for (int jj = 0; jj < 4; jj++)
                v4[jj] = *(const float4*)&Vsm[(j + jj) * 64 + d0];
#pragma unroll
            for (int ii = 0; ii < 4; ii++) {
                Oa[ii][0] = fmaf(p4[ii].x, v4[0].x, Oa[ii][0]);
                Oa[ii][1] = fmaf(p4[ii].x, v4[0].y, Oa[ii][1]);
                Oa[ii][2] = fmaf(p4[ii].x, v4[0].z, Oa[ii][2]);
                Oa[ii][3] = fmaf(p4[ii].x, v4[0].w, Oa[ii][3]);
                Oa[ii][0] = fmaf(p4[ii].y, v4[1].x, Oa[ii][0]);
                Oa[ii][1] = fmaf(p4[ii].y, v4[1].y, Oa[ii][1]);
                Oa[ii][2] = fmaf(p4[ii].y, v4[1].z, Oa[ii][2]);
                Oa[ii][3] = fmaf(p4[ii].y, v4[1].w, Oa[ii][3]);
                Oa[ii][0] = fmaf(p4[ii].z, v4[2].x, Oa[ii][0]);
                Oa[ii][1] = fmaf(p4[ii].z, v4[2].y, Oa[ii][1]);
                Oa[ii][2] = fmaf(p4[ii].z, v4[2].z, Oa[ii][2]);
                Oa[ii][3] = fmaf(p4[ii].z, v4[2].w, Oa[ii][3]);
                Oa[ii][0] = fmaf(p4[ii].w, v4[3].x, Oa[ii][0]);
                Oa[ii][1] = fmaf(p4[ii].w, v4[3].y, Oa[ii][1]);
                Oa[ii][2] = fmaf(p4[ii].w, v4[3].z, Oa[ii][2]);
                Oa[ii][3] = fmaf(p4[ii].w, v4[3].w, Oa[ii][3]);
            }
        }
    }

#pragma unroll
    for (int ii = 0; ii < 4; ii++) {
        int q = q0 + i0 + ii;
        float inv = 1.f / lrow[ii];
        float4 o;
        if (q < qlen) {
            o.x = Oa[ii][0] * inv;
            o.y = Oa[ii][1] * inv;
            o.z = Oa[ii][2] * inv;
            o.w = Oa[ii][3] * inv;
        } else {
            o = make_float4(0.f, 0.f, 0.f, 0.f);
        }
        *(float4*)(outb + (size_t)q * OD + d0) = o;
    }
}

// ---------------------------------------------------------------------------
extern "C" void kernel_launch(void* const* d_in, const int* in_sizes, int n_in,
                              void* d_out, int out_size)
{
    (void)in_sizes; (void)n_in; (void)out_size;
    const float* Qseq = (const float*)d_in[0];
    const float* Kseq = (const float*)d_in[1];
    const float* Vseq = (const float*)d_in[2];
    const int*   Qlen = (const int*)d_in[3];
    const int*   Vlen = (const int*)d_in[4];
    const float* WQw  = (const float*)d_in[5];
    const float* WQb  = (const float*)d_in[6];
    const float* WKw  = (const float*)d_in[7];
    const float* WKb  = (const float*)d_in[8];
    const float* WVw  = (const float*)d_in[9];
    const float* WVb  = (const float*)d_in[10];
    float* out = (float*)d_out;

    float *pQ = nullptr, *pK = nullptr, *pV = nullptr;
    cudaGetSymbolAddress((void**)&pQ, g_Q);
    cudaGetSymbolAddress((void**)&pK, g_K);
    cudaGetSymbolAddress((void**)&pV, g_V);

    cudaFuncSetAttribute(proj_tc,
                         cudaFuncAttributeMaxDynamicSharedMemorySize, PROJ_SMEM);
    cudaFuncSetAttribute(attn_kernel,
                         cudaFuncAttributeMaxDynamicSharedMemorySize, ATTN_SMEM);

    dim3 pg(256, 3);
    proj_tc<<<pg, 256, PROJ_SMEM>>>(Qseq, Kseq, Vseq,
                                    WQw, WKw, WVw,
                                    WQb, WKb, WVb,
                                    pQ, pK, pV);

    dim3 grid(64, 8);
    attn_kernel<<<grid, 256, ATTN_SMEM>>>(Qlen, Vlen, out);
}

// round 5
// speedup vs baseline: 2.7877x; 1.0857x over previous
#include <cuda_runtime.h>
#include <cuda_bf16.h>
#include <cstdint>

#define LL   512
#define DD   64
#define OD   1024
#define QKSCALE 0.125f

// Scratch for projected Q/K/V in [head][p][d] layout
__device__ float g_Q[64 * LL * DD];
__device__ float g_K[64 * LL * DD];
__device__ float g_V[64 * LL * DD];
// Pre-split weights (bf16 hi/lo), [mat][n][k] = [3][64][1024]
__device__ __nv_bfloat16 g_Whi[3 * 64 * OD];
__device__ __nv_bfloat16 g_Wlo[3 * 64 * OD];

// ---------------------------------------------------------------------------
__device__ __forceinline__ uint32_t smem_u32(const void* p) {
    uint32_t a;
    asm("{ .reg .u64 t; cvta.to.shared.u64 t, %1; cvt.u32.u64 %0, t; }"
        : "=r"(a) : "l"(p));
    return a;
}

__device__ __forceinline__ void ldm4(uint32_t* r, uint32_t addr) {
    asm volatile("ldmatrix.sync.aligned.m8n8.x4.shared.b16 {%0,%1,%2,%3}, [%4];"
                 : "=r"(r[0]), "=r"(r[1]), "=r"(r[2]), "=r"(r[3]) : "r"(addr));
}

__device__ __forceinline__ void mma_bf16(float* c, const uint32_t* a,
                                         const uint32_t* b) {
    asm volatile(
        "mma.sync.aligned.m16n8k16.row.col.f32.bf16.bf16.f32 "
        "{%0,%1,%2,%3}, {%4,%5,%6,%7}, {%8,%9}, {%0,%1,%2,%3};"
        : "+f"(c[0]), "+f"(c[1]), "+f"(c[2]), "+f"(c[3])
        : "r"(a[0]), "r"(a[1]), "r"(a[2]), "r"(a[3]), "r"(b[0]), "r"(b[1]));
}

// One-off: split W (fp32) into bf16 hi + lo with round-to-nearest.
__global__ void wsplit_kernel(const float* __restrict__ WQ,
                              const float* __restrict__ WK,
                              const float* __restrict__ WV)
{
    int idx = blockIdx.x * 256 + threadIdx.x;     // 0 .. 3*65536-1
    int mat = idx >> 16;
    int off = idx & 65535;
    const float* W = (mat == 0) ? WQ : (mat == 1) ? WK : WV;
    float v = W[off];
    __nv_bfloat16 h = __float2bfloat16(v);
    g_Whi[idx] = h;
    g_Wlo[idx] = __float2bfloat16(v - __bfloat162float(h));
}

// ---------------------------------------------------------------------------
// Tensor-core projection. CTA: 128 rows x 64 cols, 8 warps (4x2), 32x32 each.
// X split in-register via PRMT truncation; W pre-split (pure copy path).
// ---------------------------------------------------------------------------
#define KCH   64
#define NIT   (OD / KCH)     // 16
#define ROWP  144            // padded row bytes (72 bf16)
#define A_HI  0
#define A_LO  18432
#define B_HI  36864
#define B_LO  46080
#define PROJ_SMEM 55296

__device__ __forceinline__ void split_store_x(char* smb, uint32_t hi_off,
                                              uint32_t lo_off, float4 v) {
    uint32_t bx = __float_as_uint(v.x);
    uint32_t by = __float_as_uint(v.y);
    uint32_t bz = __float_as_uint(v.z);
    uint32_t bw = __float_as_uint(v.w);
    uint2 hv;
    hv.x = __byte_perm(bx, by, 0x7632);
    hv.y = __byte_perm(bz, bw, 0x7632);
    float lx = v.x - __uint_as_float(bx & 0xFFFF0000u);
    float ly = v.y - __uint_as_float(by & 0xFFFF0000u);
    float lz = v.z - __uint_as_float(bz & 0xFFFF0000u);
    float lw = v.w - __uint_as_float(bw & 0xFFFF0000u);
    uint2 lv;
    lv.x = __byte_perm(__float_as_uint(lx), __float_as_uint(ly), 0x7632);
    lv.y = __byte_perm(__float_as_uint(lz), __float_as_uint(lw), 0x7632);
    *(uint2*)(smb + hi_off) = hv;
    *(uint2*)(smb + lo_off) = lv;
}

__global__ __launch_bounds__(256, 2) void proj_tc(
    const float* __restrict__ Qs, const float* __restrict__ Ks,
    const float* __restrict__ Vs,
    const float* __restrict__ bQ, const float* __restrict__ bK,
    const float* __restrict__ bV,
    float* __restrict__ YQ, float* __restrict__ YK, float* __restrict__ YV)
{
    extern __shared__ char sm[];
    const int t    = threadIdx.x;
    const int wid  = t >> 5;
    const int lane = t & 31;
    const int wr   = wid & 3;
    const int wc   = wid >> 2;

    const float *X, *bias;
    float* Y;
    if (blockIdx.y == 0)      { X = Qs; bias = bQ; Y = YQ; }
    else if (blockIdx.y == 1) { X = Ks; bias = bK; Y = YK; }
    else                      { X = Vs; bias = bV; Y = YV; }
    const int mat = blockIdx.y;

    const int row0 = blockIdx.x * 128;
    const uint32_t sb = smem_u32(sm);

    const uint32_t a_row_off = (uint32_t)(wr * 32 + (lane & 15)) * ROWP
                             + ((lane >> 4) & 1) * 16;
    const uint32_t b_row_off = (uint32_t)((lane & 7) + ((lane & 16) >> 1)) * ROWP
                             + ((lane & 8) << 1);

    const int rA = t >> 4;    // 0..15
    const int cA = t & 15;    // float4 / uint2 index within 64-elem row

    const float* xbase = X + (size_t)(row0 + rA) * OD + cA * 4;
    const __nv_bfloat16* whbase = g_Whi + (size_t)mat * 64 * OD
                                + (size_t)rA * OD + cA * 4;
    const __nv_bfloat16* wlbase = g_Wlo + (size_t)mat * 64 * OD
                                + (size_t)rA * OD + cA * 4;

    float acc[2][4][4];
#pragma unroll
    for (int mt = 0; mt < 2; mt++)
#pragma unroll
        for (int nt = 0; nt < 4; nt++)
#pragma unroll
            for (int j = 0; j < 4; j++) acc[mt][nt][j] = 0.f;

    // Prologue: chunk 0 into registers
    float4 xr[8];
    uint2 wh[4], wl[4];
#pragma unroll
    for (int p = 0; p < 8; p++)
        xr[p] = *(const float4*)(xbase + (size_t)(p * 16) * OD);
#pragma unroll
    for (int p = 0; p < 4; p++) {
        wh[p] = *(const uint2*)(whbase + (size_t)(p * 16) * OD);
        wl[p] = *(const uint2*)(wlbase + (size_t)(p * 16) * OD);
    }

    for (int it = 0; it < NIT; ++it) {
#pragma unroll
        for (int p = 0; p < 8; p++) {
            uint32_t off = (uint32_t)(rA + p * 16) * ROWP + cA * 8;
            split_store_x(sm, A_HI + off, A_LO + off, xr[p]);
        }
#pragma unroll
        for (int p = 0; p < 4; p++) {
            uint32_t off = (uint32_t)(rA + p * 16) * ROWP + cA * 8;
            *(uint2*)(sm + B_HI + off) = wh[p];
            *(uint2*)(sm + B_LO + off) = wl[p];
        }
        __syncthreads();

        // Next chunk's LDGs — overlap the MMA block below.
        if (it + 1 < NIT) {
            const int k1 = (it + 1) * KCH;
#pragma unroll
            for (int p = 0; p < 8; p++)
                xr[p] = *(const float4*)(xbase + (size_t)(p * 16) * OD + k1);
#pragma unroll
            for (int p = 0; p < 4; p++) {
                wh[p] = *(const uint2*)(whbase + (size_t)(p * 16) * OD + k1);
                wl[p] = *(const uint2*)(wlbase + (size_t)(p * 16) * OD + k1);
            }
        }

#pragma unroll
        for (int ks = 0; ks < 4; ks++) {
            uint32_t ah[2][4], al[2][4];
#pragma unroll
            for (int mt = 0; mt < 2; mt++) {
                uint32_t ao = a_row_off + (uint32_t)mt * 16 * ROWP + ks * 32;
                ldm4(ah[mt], sb + A_HI + ao);
                ldm4(al[mt], sb + A_LO + ao);
            }
#pragma unroll
            for (int nb = 0; nb < 2; nb++) {
                uint32_t bo = b_row_off + (uint32_t)(wc * 32 + nb * 16) * ROWP
                            + ks * 32;
                uint32_t bh[4], bl[4];
                ldm4(bh, sb + B_HI + bo);
                ldm4(bl, sb + B_LO + bo);
#pragma unroll
                for (int mt = 0; mt < 2; mt++) {
#pragma unroll
                    for (int h = 0; h < 2; h++) {
                        float* c = acc[mt][nb * 2 + h];
                        mma_bf16(c, ah[mt], bh + h * 2);
                        mma_bf16(c, ah[mt], bl + h * 2);
                        mma_bf16(c, al[mt], bh + h * 2);
                    }
                }
            }
        }
        __syncthreads();
    }

    // Epilogue: bias + permuted store
#pragma unroll
    for (int nt = 0; nt < 4; nt++) {
        int n0 = wc * 32 + nt * 8 + (lane & 3) * 2;
        float b0 = bias[n0], b1 = bias[n0 + 1];
#pragma unroll
        for (int mt = 0; mt < 2; mt++) {
#pragma unroll
            for (int ro = 0; ro < 2; ro++) {
                int grow = row0 + wr * 32 + mt * 16 + (lane >> 2) + ro * 8;
                int b = grow >> 9, l = grow & 511;
                int x = b >> 4, m = l & 15, pp = ((b & 15) << 5) | (l >> 4);
                int hh = (x << 4) | m;
                float2 o;
                o.x = acc[mt][nt][ro * 2 + 0] + b0;
                o.y = acc[mt][nt][ro * 2 + 1] + b1;
                *(float2*)(Y + ((size_t)hh * LL + pp) * DD + n0) = o;
            }
        }
    }
}

// ---------------------------------------------------------------------------
// Flash-style attention (unchanged).
// ---------------------------------------------------------------------------
#define ATTN_SMEM ((64*64 + 64*68 + 64*64 + 64*68) * 4)

__global__ __launch_bounds__(256) void attn_kernel(
    const int* __restrict__ Q_len, const int* __restrict__ V_len,
    float* __restrict__ out)
{
    const int hh = blockIdx.x;
    const int q0 = (7 - blockIdx.y) << 6;
    const int x  = hh >> 4;
    const int m  = hh & 15;
    const int qlen = Q_len[x];
    const int vlen = V_len[x];
    const int t    = threadIdx.x;
    const int i0   = (t >> 4) << 2;
    const int lane = t & 15;
    const int d0   = lane << 2;

    float* outb = out + (size_t)x * LL * OD + (size_t)m * DD;

    if (q0 >= qlen) {
#pragma unroll
        for (int s = 0; s < 4; s++) {
            int v  = t + 256 * s;
            int r  = v >> 4;
            int dd = (v & 15) << 2;
            *(float4*)(outb + (size_t)(q0 + r) * OD + dd) =
                make_float4(0.f, 0.f, 0.f, 0.f);
        }
        return;
    }

    extern __shared__ float smf[];
    float* Qsm = smf;
    float* Ksm = smf + 64 * 64;
    float* Vsm = Ksm + 64 * 68;
    float* Psm = Vsm + 64 * 64;

    const float* Qg = g_Q + ((size_t)hh * LL + q0) * DD;
#pragma unroll
    for (int s = 0; s < 4; s++) {
        int v  = t + 256 * s;
        int r  = v >> 4;
        int dd = (v & 15) << 2;
        *(float4*)&Qsm[r * 64 + dd] = *(const float4*)(Qg + r * DD + dd);
    }

    float Oa[4][4];
    float mrow[4], lrow[4];
#pragma unroll
    for (int ii = 0; ii < 4; ii++) {
        mrow[ii] = -1e30f;
        lrow[ii] = 0.f;
#pragma unroll
        for (int dd = 0; dd < 4; dd++) Oa[ii][dd] = 0.f;
    }

    int kmax = min(q0 + 63, vlen - 1);
    int nkt  = kmax >> 6;

    for (int kt = 0; kt <= nkt; kt++) {
        const int k0 = kt << 6;
        __syncthreads();
        const float* Kg = g_K + ((size_t)hh * LL + k0) * DD;
        const float* Vg = g_V + ((size_t)hh * LL + k0) * DD;
#pragma unroll
        for (int s = 0; s < 4; s++) {
            int v  = t + 256 * s;
            int r  = v >> 4;
            int dd = (v & 15) << 2;
            *(float4*)&Ksm[r * 68 + dd] = *(const float4*)(Kg + r * DD + dd);
            *(float4*)&Vsm[r * 64 + dd] = *(const float4*)(Vg + r * DD + dd);
        }
        __syncthreads();

        float S4[4][4];
#pragma unroll
        for (int ii = 0; ii < 4; ii++)
#pragma unroll
            for (int jj = 0; jj < 4; jj++) S4[ii][jj] = 0.f;

#pragma unroll
        for (int kk = 0; kk < 64; kk += 4) {
            float4 a[4], bz[4];
#pragma unroll
            for (int ii = 0; ii < 4; ii++)
                a[ii] = *(const float4*)&Qsm[(i0 + ii) * 64 + kk];
#pragma unroll
            for (int jj = 0; jj < 4; jj++)
                bz[jj] = *(const float4*)&Ksm[(lane + 16 * jj) * 68 + kk];
#pragma unroll
            for (int ii = 0; ii < 4; ii++)
#pragma unroll
                for (int jj = 0; jj < 4; jj++) {
                    S4[ii][jj] = fmaf(a[ii].x, bz[jj].x, S4[ii][jj]);
                    S4[ii][jj] = fmaf(a[ii].y, bz[jj].y, S4[ii][jj]);
                    S4[ii][jj] = fmaf(a[ii].z, bz[jj].z, S4[ii][jj]);
                    S4[ii][jj] = fmaf(a[ii].w, bz[jj].w, S4[ii][jj]);
                }
        }

#pragma unroll
        for (int ii = 0; ii < 4; ii++) {
            int q = q0 + i0 + ii;
#pragma unroll
            for (int jj = 0; jj < 4; jj++) {
                int k = k0 + lane + 16 * jj;
                bool valid = (k <= q) && (k < vlen);
                S4[ii][jj] = valid ? S4[ii][jj] * QKSCALE : -1e30f;
            }
        }

#pragma unroll
        for (int ii = 0; ii < 4; ii++) {
            float tm = fmaxf(fmaxf(S4[ii][0], S4[ii][1]),
                             fmaxf(S4[ii][2], S4[ii][3]));
#pragma unroll
            for (int w = 1; w < 16; w <<= 1)
                tm = fmaxf(tm, __shfl_xor_sync(0xffffffffu, tm, w));
            float mn    = fmaxf(mrow[ii], tm);
            float alpha = __expf(mrow[ii] - mn);
            float rs = 0.f;
#pragma unroll
            for (int jj = 0; jj < 4; jj++) {
                float p = __expf(S4[ii][jj] - mn);
                S4[ii][jj] = p;
                rs += p;
            }
#pragma unroll
            for (int w = 1; w < 16; w <<= 1)
                rs += __shfl_xor_sync(0xffffffffu, rs, w);
            mrow[ii] = mn;
            lrow[ii] = lrow[ii] * alpha + rs;
#pragma unroll
            for (int dd = 0; dd < 4; dd++) Oa[ii][dd] *= alpha;
        }

#pragma unroll
        for (int ii = 0; ii < 4; ii++)
#pragma unroll
            for (int jj = 0; jj < 4; jj++)
                Psm[(i0 + ii) * 68 + lane + 16 * jj] = S4[ii][jj];
        __syncthreads();

#pragma unroll
        for (int j = 0; j < 64; j += 4) {
            float4 p4[4], v4[4];
#pragma unroll
            for (int ii = 0; ii < 4; ii++)
                p4[ii] = *(const float4*)&Psm[(i0 + ii) * 68 + j];
#pragma unroll
            for (int jj = 0; jj < 4; jj++)
                v4[jj] = *(const float4*)&Vsm[(j + jj) * 64 + d0];
#pragma unroll
            for (int ii = 0; ii < 4; ii++) {
                Oa[ii][0] = fmaf(p4[ii].x, v4[0].x, Oa[ii][0]);
                Oa[ii][1] = fmaf(p4[ii].x, v4[0].y, Oa[ii][1]);
                Oa[ii][2] = fmaf(p4[ii].x, v4[0].z, Oa[ii][2]);
                Oa[ii][3] = fmaf(p4[ii].x, v4[0].w, Oa[ii][3]);
                Oa[ii][0] = fmaf(p4[ii].y, v4[1].x, Oa[ii][0]);
                Oa[ii][1] = fmaf(p4[ii].y, v4[1].y, Oa[ii][1]);
                Oa[ii][2] = fmaf(p4[ii].y, v4[1].z, Oa[ii][2]);
                Oa[ii][3] = fmaf(p4[ii].y, v4[1].w, Oa[ii][3]);
                Oa[ii][0] = fmaf(p4[ii].z, v4[2].x, Oa[ii][0]);
                Oa[ii][1] = fmaf(p4[ii].z, v4[2].y, Oa[ii][1]);
                Oa[ii][2] = fmaf(p4[ii].z, v4[2].z, Oa[ii][2]);
                Oa[ii][3] = fmaf(p4[ii].z, v4[2].w, Oa[ii][3]);
                Oa[ii][0] = fmaf(p4[ii].w, v4[3].x, Oa[ii][0]);
                Oa[ii][1] = fmaf(p4[ii].w, v4[3].y, Oa[ii][1]);
                Oa[ii][2] = fmaf(p4[ii].w, v4[3].z, Oa[ii][2]);
                Oa[ii][3] = fmaf(p4[ii].w, v4[3].w, Oa[ii][3]);
            }
        }
    }

#pragma unroll
    for (int ii = 0; ii < 4; ii++) {
        int q = q0 + i0 + ii;
        float inv = 1.f / lrow[ii];
        float4 o;
        if (q < qlen) {
            o.x = Oa[ii][0] * inv;
            o.y = Oa[ii][1] * inv;
            o.z = Oa[ii][2] * inv;
            o.w = Oa[ii][3] * inv;
        } else {
            o = make_float4(0.f, 0.f, 0.f, 0.f);
        }
        *(float4*)(outb + (size_t)q * OD + d0) = o;
    }
}

// ---------------------------------------------------------------------------
extern "C" void kernel_launch(void* const* d_in, const int* in_sizes, int n_in,
                              void* d_out, int out_size)
{
    (void)in_sizes; (void)n_in; (void)out_size;
    const float* Qseq = (const float*)d_in[0];
    const float* Kseq = (const float*)d_in[1];
    const float* Vseq = (const float*)d_in[2];
    const int*   Qlen = (const int*)d_in[3];
    const int*   Vlen = (const int*)d_in[4];
    const float* WQw  = (const float*)d_in[5];
    const float* WQb  = (const float*)d_in[6];
    const float* WKw  = (const float*)d_in[7];
    const float* WKb  = (const float*)d_in[8];
    const float* WVw  = (const float*)d_in[9];
    const float* WVb  = (const float*)d_in[10];
    float* out = (float*)d_out;

    float *pQ = nullptr, *pK = nullptr, *pV = nullptr;
    cudaGetSymbolAddress((void**)&pQ, g_Q);
    cudaGetSymbolAddress((void**)&pK, g_K);
    cudaGetSymbolAddress((void**)&pV, g_V);

    cudaFuncSetAttribute(proj_tc,
                         cudaFuncAttributeMaxDynamicSharedMemorySize, PROJ_SMEM);
    cudaFuncSetAttribute(attn_kernel,
                         cudaFuncAttributeMaxDynamicSharedMemorySize, ATTN_SMEM);

    wsplit_kernel<<<768, 256>>>(WQw, WKw, WVw);

    dim3 pg(256, 3);
    proj_tc<<<pg, 256, PROJ_SMEM>>>(Qseq, Kseq, Vseq,
                                    WQb, WKb, WVb,
                                    pQ, pK, pV);

    dim3 grid(64, 8);
    attn_kernel<<<grid, 256, ATTN_SMEM>>>(Qlen, Vlen, out);
}